// round 4
// baseline (speedup 1.0000x reference)
#include <cuda_runtime.h>
#include <cuda_bf16.h>

#define Bn   8
#define Cn   256
#define Gn   32
#define Hn   56
#define Wn   56
#define HWn  3136        // 56*56
#define QW   14          // float4 quads per row
#define NPART 2          // channel-quads per (b,g,h,q)
#define NCH   4          // channels per thread
#define TOTAL_THREADS (Bn*Gn*Hn*QW*NPART)   // 401408

__device__ __forceinline__ unsigned long long mk_policy() {
    unsigned long long pol;
    asm("createpolicy.fractional.L2::evict_last.b64 %0, 1.0;" : "=l"(pol));
    return pol;
}
__device__ __forceinline__ float4 ldg_el_f4(const float* p, unsigned long long pol) {
    float4 v;
    asm("ld.global.L2::cache_hint.v4.f32 {%0,%1,%2,%3}, [%4], %5;"
        : "=f"(v.x), "=f"(v.y), "=f"(v.z), "=f"(v.w) : "l"(p), "l"(pol));
    return v;
}
__device__ __forceinline__ float ldg_el_f(const float* p, unsigned long long pol) {
    float v;
    asm("ld.global.L2::cache_hint.f32 %0, [%1], %2;" : "=f"(v) : "l"(p), "l"(pol));
    return v;
}
__device__ __forceinline__ void stg_el_f4(float* p, float4 v, unsigned long long pol) {
    asm volatile("st.global.L2::cache_hint.v4.f32 [%0], {%1,%2,%3,%4}, %5;"
        :: "l"(p), "f"(v.x), "f"(v.y), "f"(v.z), "f"(v.w), "l"(pol) : "memory");
}

__global__ __launch_bounds__(128, 10)
void SKA_20950850470021_kernel(const float* __restrict__ x,
                               const float* __restrict__ w,
                               float* __restrict__ out) {
    int idx = blockIdx.x * blockDim.x + threadIdx.x;

    int q = idx % QW;
    int t = idx / QW;
    int h = t % Hn;
    t /= Hn;
    int g = t % Gn;
    t /= Gn;
    int b = t % Bn;
    int p = t / Bn;          // 0..1 : which quad of channels

    const unsigned long long pol = mk_policy();

    const int w0 = q * 4;
    const bool hasL = (q > 0);
    const bool hasR = (q < QW - 1);

    // weight base for this (b,g); tap k lives at +k*HWn
    const float* wbase = w + ((b * Gn + g) * 9) * HWn + h * Wn + w0;

    // x/out base for channel c = (p*4 + j)*32 + g
    const int base = (b * Cn + g) * HWn + h * Wn + w0;

    float4 acc[NCH];
#pragma unroll
    for (int j = 0; j < NCH; ++j) acc[j] = make_float4(0.f, 0.f, 0.f, 0.f);

#pragma unroll
    for (int r = 0; r < 3; ++r) {
        int hh = h + r - 1;
        if (hh < 0 || hh >= Hn) continue;   // border row: weights would multiply zeros

        const float* wr = wbase + (3 * r) * HWn;
        float4 wk0 = ldg_el_f4(wr, pol);
        float4 wk1 = ldg_el_f4(wr + HWn, pol);
        float4 wk2 = ldg_el_f4(wr + 2 * HWn, pol);

#pragma unroll
        for (int j = 0; j < NCH; ++j) {
            const float* xr = x + base + (p * NCH + j) * Gn * HWn + (r - 1) * Wn;
            float4 c = ldg_el_f4(xr, pol);
            float  l  = hasL ? ldg_el_f(xr - 1, pol) : 0.f;
            float  rr = hasR ? ldg_el_f(xr + 4, pol) : 0.f;
            acc[j].x += l   * wk0.x + c.x * wk1.x + c.y * wk2.x;
            acc[j].y += c.x * wk0.y + c.y * wk1.y + c.z * wk2.y;
            acc[j].z += c.y * wk0.z + c.z * wk1.z + c.w * wk2.z;
            acc[j].w += c.z * wk0.w + c.w * wk1.w + rr  * wk2.w;
        }
    }

#pragma unroll
    for (int j = 0; j < NCH; ++j)
        stg_el_f4(out + base + (p * NCH + j) * Gn * HWn, acc[j], pol);
}

extern "C" void kernel_launch(void* const* d_in, const int* in_sizes, int n_in,
                              void* d_out, int out_size) {
    const float* x = (const float*)d_in[0];   // (8,256,56,56)
    const float* w = (const float*)d_in[1];   // (8,32,9,56,56)
    float* out = (float*)d_out;               // (8,256,56,56)

    const int threads = 128;
    const int blocks = TOTAL_THREADS / threads;  // 3136
    SKA_20950850470021_kernel<<<blocks, threads>>>(x, w, out);
}

// round 5
// speedup vs baseline: 1.1407x; 1.1407x over previous
#include <cuda_runtime.h>
#include <cuda_bf16.h>

#define Bn   8
#define Cn   256
#define Gn   32
#define Hn   56
#define Wn   56
#define HWn  3136        // 56*56
#define QW   14          // float4 quads per row
#define NPART 4          // channel-pairs per (b,g,h,q)
#define NCH   2          // channels per thread
#define TOTAL_THREADS (Bn*Gn*Hn*QW*NPART)   // 802816

__global__ __launch_bounds__(128, 5)
void SKA_20950850470021_kernel(const float* __restrict__ x,
                               const float* __restrict__ w,
                               float* __restrict__ out) {
    int idx = blockIdx.x * blockDim.x + threadIdx.x;

    int q = idx % QW;
    int t = idx / QW;
    int h = t % Hn;
    t /= Hn;
    int g = t % Gn;
    t /= Gn;
    int b = t % Bn;
    int p = t / Bn;          // 0..3 : which pair of channels

    const int w0 = q * 4;
    const float hasLf = (q > 0) ? 1.f : 0.f;
    const float hasRf = (q < QW - 1) ? 1.f : 0.f;
    const int   dL = (q > 0) ? -1 : 0;          // safe left-edge offset
    const int   dR = (q < QW - 1) ? 4 : 0;      // safe right-edge offset

    // row validity (r = 0,1,2 -> hh = h-1, h, h+1); clamp offset for safe loads
    const float fv0 = (h > 0) ? 1.f : 0.f;
    const float fv2 = (h < Hn - 1) ? 1.f : 0.f;
    const int roff[3] = { (h > 0) ? -Wn : 0, 0, (h < Hn - 1) ? Wn : 0 };
    const float fv[3] = { fv0, 1.f, fv2 };

    // ---------------- load phase: everything front-batched ----------------
    const float* wbase = w + ((b * Gn + g) * 9) * HWn + h * Wn + w0;
    float4 wk[9];
#pragma unroll
    for (int k = 0; k < 9; ++k)
        wk[k] = *reinterpret_cast<const float4*>(wbase + k * HWn);

    const int base = (b * Cn + g) * HWn + h * Wn + w0;
    float4 cen[NCH][3];
    float  lf [NCH][3];
    float  rf [NCH][3];
#pragma unroll
    for (int j = 0; j < NCH; ++j) {
        const float* xc = x + base + (p * NCH + j) * Gn * HWn;
#pragma unroll
        for (int r = 0; r < 3; ++r) {
            const float* xr = xc + roff[r];
            cen[j][r] = *reinterpret_cast<const float4*>(xr);
            lf [j][r] = xr[dL];
            rf [j][r] = xr[dR];
        }
    }

    // ---------------- compute phase ----------------
    // fold row validity into the weights (shared by both channels),
    // and edge validity into the edge scalars.
#pragma unroll
    for (int k = 0; k < 9; ++k) {
        const float s = fv[k / 3];
        wk[k].x *= s; wk[k].y *= s; wk[k].z *= s; wk[k].w *= s;
    }
#pragma unroll
    for (int j = 0; j < NCH; ++j)
#pragma unroll
        for (int r = 0; r < 3; ++r) {
            lf[j][r] *= hasLf;
            rf[j][r] *= hasRf;
        }

    float4 acc[NCH];
#pragma unroll
    for (int j = 0; j < NCH; ++j) {
        float4 a = make_float4(0.f, 0.f, 0.f, 0.f);
#pragma unroll
        for (int r = 0; r < 3; ++r) {
            const float4 wk0 = wk[r * 3 + 0];
            const float4 wk1 = wk[r * 3 + 1];
            const float4 wk2 = wk[r * 3 + 2];
            const float4 c = cen[j][r];
            a.x += lf[j][r] * wk0.x + c.x * wk1.x + c.y * wk2.x;
            a.y += c.x * wk0.y + c.y * wk1.y + c.z * wk2.y;
            a.z += c.y * wk0.z + c.z * wk1.z + c.w * wk2.z;
            a.w += c.z * wk0.w + c.w * wk1.w + rf[j][r] * wk2.w;
        }
        acc[j] = a;
    }

#pragma unroll
    for (int j = 0; j < NCH; ++j)
        *reinterpret_cast<float4*>(out + base + (p * NCH + j) * Gn * HWn) = acc[j];
}

extern "C" void kernel_launch(void* const* d_in, const int* in_sizes, int n_in,
                              void* d_out, int out_size) {
    const float* x = (const float*)d_in[0];   // (8,256,56,56)
    const float* w = (const float*)d_in[1];   // (8,32,9,56,56)
    float* out = (float*)d_out;               // (8,256,56,56)

    const int threads = 128;
    const int blocks = TOTAL_THREADS / threads;  // 6272
    SKA_20950850470021_kernel<<<blocks, threads>>>(x, w, out);
}